// round 10
// baseline (speedup 1.0000x reference)
#include <cuda_runtime.h>
#include <cuda_bf16.h>

#define EPS 1e-6f
#define NB 16
#define NA 10
#define NT 30
#define NP_POLY 16
#define NV 200
#define SEG_PER_POLY (NV - 1)            // 199
#define NSEG (NP_POLY * SEG_PER_POLY)    // 3184 per batch
#define NPTS_WARP 10
#define WARPS 3
#define THREADS (WARPS * 32)             // 96: 3 warps x 10 pts = 30 = NT
#define NBA (NB * NA)                    // 160
#define GRID (NBA * NP_POLY)             // 2560

// per-(batch,segment) precomputed tables
__device__ float4 g_segA[NB * NSEG];  // {sx, sy, evx, evy}
__device__ float4 g_segB[NB * NSEG];  // {ey, 1/(esq+eps), 1/(slope+eps), 0}

// partial results: [ba][t][poly]  (poly contiguous -> float4/int4 reads)
__device__ float g_md[NBA * NT * NP_POLY];
__device__ int   g_ct[NBA * NT * NP_POLY];
__device__ unsigned g_cnt[NBA];       // zero-init; reset by folding block

__device__ __forceinline__ unsigned warp_redux_min_u32(unsigned v) {
    unsigned r;
    asm("redux.sync.min.u32 %0, %1, 0xffffffff;" : "=r"(r) : "r"(v));
    return r;
}
__device__ __forceinline__ int warp_redux_add_s32(int v) {
    int r;
    asm("redux.sync.add.s32 %0, %1, 0xffffffff;" : "=r"(r) : "r"(v));
    return r;
}
__device__ __forceinline__ unsigned atom_add_acqrel(unsigned* p, unsigned v) {
    unsigned old;
    asm volatile("atom.acq_rel.gpu.global.add.u32 %0, [%1], %2;"
                 : "=r"(old) : "l"(p), "r"(v) : "memory");
    return old;
}

__global__ void precompute_kernel(const float* __restrict__ polys) {
    int idx = blockIdx.x * blockDim.x + threadIdx.x;
    if (idx >= NB * NSEG) return;
    int b = idx / NSEG;
    int s = idx - b * NSEG;
    int p = s / SEG_PER_POLY;
    int j = s - p * SEG_PER_POLY;
    const float* v = polys + (((size_t)b * NP_POLY + p) * NV + j) * 2;
    float sx = v[0], sy = v[1], ex = v[2], ey = v[3];
    float evx = ex - sx;                    // same IEEE subs as reference
    float evy = ey - sy;
    float esq = fmaf(evx, evx, evy * evy);
    float rcp_esq = 1.0f / (esq + EPS);
    float slope = evy / (evx + EPS);
    float rcp_sl = 1.0f / (slope + EPS);
    g_segA[idx] = make_float4(sx, sy, evx, evy);
    g_segB[idx] = make_float4(ey, rcp_esq, rcp_sl, 0.0f);
}

__global__ __launch_bounds__(THREADS)
void offroad_main_kernel(const float* __restrict__ points,
                         float* __restrict__ out) {
    __shared__ int s_doFold;

    int bx = blockIdx.x;
    int p  = bx & (NP_POLY - 1);
    int ba = bx >> 4;                    // b*NA + a
    int b  = ba / NA;

    int wid = threadIdx.x >> 5;
    int ln  = threadIdx.x & 31;
    int t0  = wid * NPTS_WARP;           // 0,10,20 -> all valid

    float px[NPTS_WARP], py[NPTS_WARP], md[NPTS_WARP];
    int   ct[NPTS_WARP];

    const float2* pts2 = (const float2*)points;
#pragma unroll
    for (int k = 0; k < NPTS_WARP; k++) {
        float2 pt = pts2[ba * NT + t0 + k];
        px[k] = pt.x; py[k] = pt.y;
        md[k] = 3.4e38f;
        ct[k] = 0;
    }

    const float4* sA = g_segA + (b * NSEG + p * SEG_PER_POLY);
    const float4* sB = g_segB + (b * NSEG + p * SEG_PER_POLY);

#pragma unroll 1
    for (int s = ln; s < SEG_PER_POLY; s += 32) {
        float4 a = __ldg(&sA[s]);        // {sx, sy, evx, evy}
        float4 q = __ldg(&sB[s]);        // {ey, rcp_esq, rcp_sl, -}
#pragma unroll
        for (int k = 0; k < NPTS_WARP; k++) {
            float v1x = px[k] - a.x;
            float v1y = py[k] - a.y;
            float dot = fmaf(v1x, a.z, v1y * a.w);
            float proj = __saturatef(dot * q.y);
            float dx = fmaf(-a.z, proj, v1x);
            float dy = fmaf(-a.w, proj, v1y);
            float d2 = fmaf(dx, dx, dy * dy);
            md[k] = fminf(md[k], d2);
            bool c1 = (a.y <= py[k]);
            bool c2 = (q.x <= py[k]);
            float ix = fmaf(v1y, q.z, a.x);
            ct[k] += ((c1 != c2) & (ix > px[k])) ? 1 : 0;
        }
    }

    // per-point warp fold (redux: bit-min of nonneg f32 == float min; add exact)
#pragma unroll
    for (int k = 0; k < NPTS_WARP; k++) {
        unsigned mb = warp_redux_min_u32(__float_as_uint(md[k]));
        int      cc = warp_redux_add_s32(ct[k]);
        if (ln == 0) {
            int idx = (ba * NT + t0 + k) * NP_POLY + p;
            g_md[idx] = __uint_as_float(mb);
            g_ct[idx] = cc;
        }
    }

    // ---- per-ba completion counter (release-after-barrier pattern) ----
    __syncthreads();                     // all warps' partial stores done
    if (threadIdx.x == 0) {
        unsigned old = atom_add_acqrel(&g_cnt[ba], 1u);   // release: publishes block's stores
        s_doFold = (old == (unsigned)(NP_POLY - 1));
        if (s_doFold) g_cnt[ba] = 0;     // reset for next graph replay
    }
    __syncthreads();

    // ---- 16th arriver folds this ba (acquire on the atomic above) ----
    if (s_doFold && wid == 0) {
        float loss = 0.0f;
        if (ln < NT) {
            const float4* pm = (const float4*)(g_md + (ba * NT + ln) * NP_POLY);
            const int4*   pc = (const int4*)  (g_ct + (ba * NT + ln) * NP_POLY);
            float m = 3.4e38f;
            int   c = 0;
#pragma unroll
            for (int q = 0; q < NP_POLY / 4; q++) {
                float4 mv = __ldcg(&pm[q]);   // L2 reads (skip possibly-stale L1)
                int4   cv = __ldcg(&pc[q]);
                m = fminf(m, fminf(fminf(mv.x, mv.y), fminf(mv.z, mv.w)));
                c += cv.x + cv.y + cv.z + cv.w;
            }
            float d = sqrtf(fmaxf(m, EPS));
            if (c & 1) d = -d;
            loss = fmaxf(d + 0.5f, 0.0f);
        }
        // deterministic fixed-tree sum over t (lanes 30,31 contribute 0)
#pragma unroll
        for (int o = 16; o > 0; o >>= 1)
            loss += __shfl_xor_sync(0xffffffffu, loss, o);
        if (ln == 0) out[ba] = loss;
    }
}

extern "C" void kernel_launch(void* const* d_in, const int* in_sizes, int n_in,
                              void* d_out, int out_size) {
    const float* points = (const float*)d_in[0];  // (16,10,30,2)
    const float* polys  = (const float*)d_in[1];  // (16,16,200,2)
    float* out = (float*)d_out;                   // (16,10)

    int total = NB * NSEG;
    precompute_kernel<<<(total + 255) / 256, 256>>>(polys);
    offroad_main_kernel<<<GRID, THREADS>>>(points, out);
}